// round 2
// baseline (speedup 1.0000x reference)
#include <cuda_runtime.h>
#include <math.h>

// ---------------- problem constants ----------------
#define NN     8191        // total tree nodes
#define NINT   4095        // internal nodes (0..4094), leaves 4095..8190
#define SNPX   5000        // SNPS * ALPHA
#define DD     1600        // tree-LSTM hidden dim
#define IDDIM  32
#define KIN    1632        // DD + IDDIM
#define FD     3232        // fusion feature dim = 2*DD + IDDIM
#define YW     192         // fc0 pieces: 3 * 64
#define NIOU   4800        // 3 * DD (i|o|u packed)

// ---------------- scratch (static device memory) ----------------
__device__ float g_feat[(size_t)NN * FD];        // [x_int | h | idd]
__device__ float g_c[(size_t)NN * DD];
__device__ float g_xin_iou[(size_t)2048 * KIN];  // [idd | hl+hr]
__device__ float g_xin_f[(size_t)4096 * KIN];    // [idd | hl],[idd | hr]
__device__ float g_pre_iou[(size_t)2048 * NIOU]; // [i | o | u] pre-activations
__device__ float g_pre_f[(size_t)4096 * DD];
__device__ float g_y[(size_t)NN * YW];
__device__ float g_w012[(size_t)YW * FD];        // packed fc0 weight
__device__ float g_wiou[(size_t)NIOU * KIN];     // [Wi; Wo; Wu]

__device__ __forceinline__ float sigmoidf(float x) { return 1.0f / (1.0f + expf(-x)); }

// ---------------- conv front-end -------------------------------------------
__global__ void conv_kernel(const float* __restrict__ x,
                            const float* __restrict__ idd,
                            const float* __restrict__ cw, const float* __restrict__ cb,
                            const float* __restrict__ lw, const float* __restrict__ lb)
{
    __shared__ float xs[SNPX];
    __shared__ float pwi[200];
    __shared__ float pwl[200];
    const int n = blockIdx.x;
    const float* xr = x + (size_t)n * SNPX;
    for (int i = threadIdx.x; i < SNPX / 4; i += blockDim.x)
        ((float4*)xs)[i] = ((const float4*)xr)[i];
    if (threadIdx.x < 200) {
        int co = threadIdx.x / 25, off = threadIdx.x % 25;
        int widx = co * 25 + (off % 5) * 5 + (off / 5);
        pwi[threadIdx.x] = cw[widx];
        pwl[threadIdx.x] = lw[widx];
    }
    if (threadIdx.x >= 224) {
        int j = threadIdx.x - 224;
        g_feat[(size_t)n * FD + 3200 + j] = idd[(size_t)n * IDDIM + j];
    }
    __syncthreads();

    const bool leaf = (n >= NINT);
    const int t = threadIdx.x;
    if (t < 200) {
        const float* xp = &xs[25 * t];
        #pragma unroll
        for (int co = 0; co < 8; co++) {
            float acc = cb[co];
            #pragma unroll
            for (int off = 0; off < 25; off++) acc += xp[off] * pwi[co * 25 + off];
            g_feat[(size_t)n * FD + co * 200 + t] = fmaxf(acc, 0.0f);
        }
        if (leaf) {
            #pragma unroll
            for (int co = 0; co < 8; co++) {
                float acc = lb[co];
                #pragma unroll
                for (int off = 0; off < 25; off++) acc += xp[off] * pwl[co * 25 + off];
                g_feat[(size_t)n * FD + DD + co * 200 + t] = fmaxf(acc, 0.0f);
            }
        }
    }
    if (leaf) {
        for (int j = threadIdx.x; j < DD; j += blockDim.x)
            g_c[(size_t)n * DD + j] = 0.0f;
    }
}

// ---------------- SGEMM: C[M,N] = A[M,K] @ B[N,K]^T -------------------------
// 128x128x16 tile, 256 threads, 8x8 micro-tile, warp-tiled 32(M)x64(N).
// Requires K % 16 == 0 and N % 8 == 0; M,N guarded.
__global__ void __launch_bounds__(256)
sgemm128(const float* __restrict__ A, int lda,
         const float* __restrict__ B, int ldb,
         float* __restrict__ C, int ldc,
         int M, int N, int K)
{
    __shared__ float As[16][128];
    __shared__ float Bs[16][128];
    const int tid = threadIdx.x;
    const int rowBase = blockIdx.y * 128;
    const int colBase = blockIdx.x * 128;
    const int ldr = tid >> 1;            // 0..127 tile row
    const int ldk = (tid & 1) * 8;       // 0 or 8 k offset
    const int w = tid >> 5;
    const int lane = tid & 31;
    const int rm = (w & 3) * 32 + (lane & 3) * 8;   // M micro base within tile
    const int cn = (w >> 2) * 64 + (lane >> 2) * 8; // N micro base within tile

    const float* Aptr = A + (size_t)(rowBase + ldr) * lda + ldk;
    const float* Bptr = B + (size_t)(colBase + ldr) * ldb + ldk;
    const bool aval = (rowBase + ldr) < M;
    const bool bval = (colBase + ldr) < N;

    float acc[8][8] = {};
    for (int k0 = 0; k0 < K; k0 += 16) {
        float4 a0 = make_float4(0.f,0.f,0.f,0.f), a1 = a0, b0 = a0, b1 = a0;
        if (aval) { a0 = *(const float4*)(Aptr + k0); a1 = *(const float4*)(Aptr + k0 + 4); }
        if (bval) { b0 = *(const float4*)(Bptr + k0); b1 = *(const float4*)(Bptr + k0 + 4); }
        As[ldk+0][ldr]=a0.x; As[ldk+1][ldr]=a0.y; As[ldk+2][ldr]=a0.z; As[ldk+3][ldr]=a0.w;
        As[ldk+4][ldr]=a1.x; As[ldk+5][ldr]=a1.y; As[ldk+6][ldr]=a1.z; As[ldk+7][ldr]=a1.w;
        Bs[ldk+0][ldr]=b0.x; Bs[ldk+1][ldr]=b0.y; Bs[ldk+2][ldr]=b0.z; Bs[ldk+3][ldr]=b0.w;
        Bs[ldk+4][ldr]=b1.x; Bs[ldk+5][ldr]=b1.y; Bs[ldk+6][ldr]=b1.z; Bs[ldk+7][ldr]=b1.w;
        __syncthreads();
        #pragma unroll
        for (int k = 0; k < 16; k++) {
            float4 ra0 = *(const float4*)&As[k][rm];
            float4 ra1 = *(const float4*)&As[k][rm + 4];
            float4 rb0 = *(const float4*)&Bs[k][cn];
            float4 rb1 = *(const float4*)&Bs[k][cn + 4];
            float a[8] = {ra0.x, ra0.y, ra0.z, ra0.w, ra1.x, ra1.y, ra1.z, ra1.w};
            float b[8] = {rb0.x, rb0.y, rb0.z, rb0.w, rb1.x, rb1.y, rb1.z, rb1.w};
            #pragma unroll
            for (int i = 0; i < 8; i++)
                #pragma unroll
                for (int j = 0; j < 8; j++)
                    acc[i][j] += a[i] * b[j];
        }
        __syncthreads();
    }
    #pragma unroll
    for (int i = 0; i < 8; i++) {
        int r = rowBase + rm + i;
        if (r < M) {
            int c0 = colBase + cn;
            if (c0 < N)
                *(float4*)&C[(size_t)r * ldc + c0] =
                    make_float4(acc[i][0], acc[i][1], acc[i][2], acc[i][3]);
            if (c0 + 4 < N)
                *(float4*)&C[(size_t)r * ldc + c0 + 4] =
                    make_float4(acc[i][4], acc[i][5], acc[i][6], acc[i][7]);
        }
    }
}

// ---------------- per-level LSTM input build -------------------------------
__global__ void build_xin(int start, const float* __restrict__ idd)
{
    const int t = blockIdx.x;
    const int p = start + t;
    const int l = 2 * p + 1, r = 2 * p + 2;
    const float* hl = &g_feat[(size_t)l * FD + DD];
    const float* hr = &g_feat[(size_t)r * FD + DD];
    float* xiou = &g_xin_iou[(size_t)t * KIN];
    float* xfl  = &g_xin_f[(size_t)(2 * t) * KIN];
    float* xfr  = &g_xin_f[(size_t)(2 * t + 1) * KIN];
    for (int j = threadIdx.x; j < IDDIM; j += blockDim.x) {
        float v = idd[(size_t)p * IDDIM + j];
        xiou[j] = v; xfl[j] = v; xfr[j] = v;
    }
    for (int j = threadIdx.x; j < DD; j += blockDim.x) {
        float a = hl[j], b = hr[j];
        xiou[IDDIM + j] = a + b;
        xfl[IDDIM + j] = a;
        xfr[IDDIM + j] = b;
    }
}

// ---------------- per-level LSTM pointwise combine -------------------------
__global__ void lstm_combine(int start,
                             const float* __restrict__ bi, const float* __restrict__ bf,
                             const float* __restrict__ bu, const float* __restrict__ bo)
{
    const int t = blockIdx.x;
    const int p = start + t;
    const int l = 2 * p + 1, r = 2 * p + 2;
    const float* pre = &g_pre_iou[(size_t)t * NIOU];
    for (int j = threadIdx.x; j < DD; j += blockDim.x) {
        float vi = sigmoidf(pre[j]            + bi[j]);
        float vo = sigmoidf(pre[DD + j]       + bo[j]);
        float vu = tanhf  (pre[2 * DD + j]    + bu[j]);
        float fl = sigmoidf(g_pre_f[(size_t)(2 * t) * DD + j]     + bf[j]);
        float fr = sigmoidf(g_pre_f[(size_t)(2 * t + 1) * DD + j] + bf[j]);
        float cn = vi * vu + fl * g_c[(size_t)l * DD + j] + fr * g_c[(size_t)r * DD + j];
        g_c[(size_t)p * DD + j] = cn;
        g_feat[(size_t)p * FD + DD + j] = vo * tanhf(cn);
    }
}

// ---------------- pack fc0 weight [192,3232] -------------------------------
__global__ void pack_w012(const float* __restrict__ fc0_w)
{
    int idx = blockIdx.x * blockDim.x + threadIdx.x;
    if (idx >= YW * FD) return;
    int r = idx / FD, k = idx % FD;
    g_w012[idx] = fc0_w[(size_t)(r & 63) * (3 * FD) + (size_t)(r >> 6) * FD + k];
}

// ---------------- head: fusion combine + fc1 + fc2 -------------------------
__global__ void head_kernel(const float* __restrict__ fc0_b,
                            const float* __restrict__ fc1_w, const float* __restrict__ fc1_b,
                            const float* __restrict__ fc2_w, const float* __restrict__ fc2_b,
                            float* __restrict__ out)
{
    __shared__ float z[64];
    __shared__ float z1[64];
    __shared__ float partial[2];
    const int n = blockIdx.x;
    const int j = threadIdx.x;

    float acc = fc0_b[j] + g_y[(size_t)n * YW + j];
    if (n > 0) {
        int par = (n - 1) >> 1;
        acc += g_y[(size_t)par * YW + 64 + j];
    }
    if (n < NINT) {
        acc += 0.5f * (g_y[(size_t)(2 * n + 1) * YW + 128 + j] +
                       g_y[(size_t)(2 * n + 2) * YW + 128 + j]);
    }
    z[j] = fmaxf(acc, 0.0f);
    __syncthreads();

    float a1 = fc1_b[j];
    #pragma unroll 8
    for (int k = 0; k < 64; k++) a1 += fc1_w[j * 64 + k] * z[k];
    z1[j] = fmaxf(a1, 0.0f);
    __syncthreads();

    float v = fc2_w[j] * z1[j];
    #pragma unroll
    for (int off = 16; off > 0; off >>= 1) v += __shfl_down_sync(0xffffffffu, v, off);
    if ((j & 31) == 0) partial[j >> 5] = v;
    __syncthreads();
    if (j == 0) out[n] = partial[0] + partial[1] + fc2_b[0];
}

// ---------------- launch ----------------------------------------------------
extern "C" void kernel_launch(void* const* d_in, const int* in_sizes, int n_in,
                              void* d_out, int out_size)
{
    const float* x      = (const float*)d_in[0];
    const float* idd    = (const float*)d_in[1];
    const float* conv_w  = (const float*)d_in[4];
    const float* conv_b  = (const float*)d_in[5];
    const float* convl_w = (const float*)d_in[6];
    const float* convl_b = (const float*)d_in[7];
    const float* Wi = (const float*)d_in[8];   const float* bi = (const float*)d_in[9];
    const float* Wf = (const float*)d_in[10];  const float* bf = (const float*)d_in[11];
    const float* Wu = (const float*)d_in[12];  const float* bu = (const float*)d_in[13];
    const float* Wo = (const float*)d_in[14];  const float* bo = (const float*)d_in[15];
    const float* fc0_w = (const float*)d_in[16]; const float* fc0_b = (const float*)d_in[17];
    const float* fc1_w = (const float*)d_in[18]; const float* fc1_b = (const float*)d_in[19];
    const float* fc2_w = (const float*)d_in[20]; const float* fc2_b = (const float*)d_in[21];
    float* out = (float*)d_out;

    float *p_xin_iou, *p_xin_f, *p_pre_iou, *p_pre_f, *p_feat, *p_y, *p_w012, *p_wiou;
    cudaGetSymbolAddress((void**)&p_xin_iou, g_xin_iou);
    cudaGetSymbolAddress((void**)&p_xin_f,   g_xin_f);
    cudaGetSymbolAddress((void**)&p_pre_iou, g_pre_iou);
    cudaGetSymbolAddress((void**)&p_pre_f,   g_pre_f);
    cudaGetSymbolAddress((void**)&p_feat,    g_feat);
    cudaGetSymbolAddress((void**)&p_y,       g_y);
    cudaGetSymbolAddress((void**)&p_w012,    g_w012);
    cudaGetSymbolAddress((void**)&p_wiou,    g_wiou);

    const size_t wbytes = (size_t)DD * KIN * sizeof(float);

    // 0) pack WIOU = [Wi; Wo; Wu] via D2D copies (graph-capturable)
    cudaMemcpyAsync(p_wiou,               Wi, wbytes, cudaMemcpyDeviceToDevice, 0);
    cudaMemcpyAsync(p_wiou + (size_t)DD * KIN,     Wo, wbytes, cudaMemcpyDeviceToDevice, 0);
    cudaMemcpyAsync(p_wiou + (size_t)2 * DD * KIN, Wu, wbytes, cudaMemcpyDeviceToDevice, 0);

    // 1) conv front-end
    conv_kernel<<<NN, 256>>>(x, idd, conv_w, conv_b, convl_w, convl_b);

    // 2) pack fc0 weight blocks
    pack_w012<<<(YW * FD + 255) / 256, 256>>>(fc0_w);

    // 3) bottom-up tree LSTM
    for (int depth = 11; depth >= 0; depth--) {
        int m = 1 << depth;
        int start = m - 1;
        build_xin<<<m, 256>>>(start, idd);
        dim3 g1((NIOU + 127) / 128, (m + 127) / 128);
        sgemm128<<<g1, 256>>>(p_xin_iou, KIN, p_wiou, KIN, p_pre_iou, NIOU, m, NIOU, KIN);
        dim3 g2((DD + 127) / 128, (2 * m + 127) / 128);
        sgemm128<<<g2, 256>>>(p_xin_f, KIN, Wf, KIN, p_pre_f, DD, 2 * m, DD, KIN);
        lstm_combine<<<m, 256>>>(start, bi, bf, bu, bo);
    }

    // 4) fused fc0: Y[N,192] = feat @ [W0a;W0b;W0c]^T
    dim3 g3((YW + 127) / 128, (NN + 127) / 128);
    sgemm128<<<g3, 256>>>(p_feat, FD, p_w012, FD, p_y, YW, NN, YW, FD);

    // 5) fusion combine + fc1 + fc2
    head_kernel<<<NN, 64>>>(fc0_b, fc1_w, fc1_b, fc2_w, fc2_b, out);
}

// round 3
// speedup vs baseline: 1.8965x; 1.8965x over previous
#include <cuda_runtime.h>
#include <math.h>

// ---------------- problem constants ----------------
#define NN     8191        // total tree nodes
#define NINT   4095        // internal nodes (0..4094), leaves 4095..8190
#define SNPX   5000        // SNPS * ALPHA
#define DD     1600        // tree-LSTM hidden dim
#define IDDIM  32
#define KIN    1632        // DD + IDDIM
#define FD     3232        // fusion feature dim = 2*DD + IDDIM
#define YW     192         // fc0 pieces: 3 * 64
#define NIOU   4800        // 3 * DD (i|o|u packed)
#define SFC0   4           // split-K for fc0

// ---------------- scratch (static device memory) ----------------
__device__ float g_feat[(size_t)NN * FD];        // [x_int | h | idd]
__device__ float g_c[(size_t)NN * DD];
__device__ float g_xin_iou[(size_t)2048 * KIN];  // [idd | hl+hr]
__device__ float g_xin_f[(size_t)4096 * KIN];    // [idd | hl],[idd | hr]
__device__ float g_pre_iou[(size_t)2048 * NIOU]; // S*m <= 2048 partial rows
__device__ float g_pre_f[(size_t)4096 * DD];     // S*2m <= 4096 partial rows
__device__ float g_y[(size_t)SFC0 * NN * YW];    // fc0 split-K partials
__device__ float g_w012[(size_t)YW * FD];        // packed fc0 weight
__device__ float g_wiou[(size_t)NIOU * KIN];     // [Wi; Wo; Wu]

__device__ __forceinline__ float sigmoidf(float x) { return 1.0f / (1.0f + expf(-x)); }

// ---------------- conv front-end -------------------------------------------
__global__ void conv_kernel(const float* __restrict__ x,
                            const float* __restrict__ idd,
                            const float* __restrict__ cw, const float* __restrict__ cb,
                            const float* __restrict__ lw, const float* __restrict__ lb)
{
    __shared__ float xs[SNPX];
    __shared__ float pwi[200];
    __shared__ float pwl[200];
    const int n = blockIdx.x;
    const float* xr = x + (size_t)n * SNPX;
    for (int i = threadIdx.x; i < SNPX / 4; i += blockDim.x)
        ((float4*)xs)[i] = ((const float4*)xr)[i];
    if (threadIdx.x < 200) {
        int co = threadIdx.x / 25, off = threadIdx.x % 25;
        int widx = co * 25 + (off % 5) * 5 + (off / 5);
        pwi[threadIdx.x] = cw[widx];
        pwl[threadIdx.x] = lw[widx];
    }
    if (threadIdx.x >= 224) {
        int j = threadIdx.x - 224;
        g_feat[(size_t)n * FD + 3200 + j] = idd[(size_t)n * IDDIM + j];
    }
    __syncthreads();

    const bool leaf = (n >= NINT);
    const int t = threadIdx.x;
    if (t < 200) {
        const float* xp = &xs[25 * t];
        #pragma unroll
        for (int co = 0; co < 8; co++) {
            float acc = cb[co];
            #pragma unroll
            for (int off = 0; off < 25; off++) acc += xp[off] * pwi[co * 25 + off];
            g_feat[(size_t)n * FD + co * 200 + t] = fmaxf(acc, 0.0f);
        }
        if (leaf) {
            #pragma unroll
            for (int co = 0; co < 8; co++) {
                float acc = lb[co];
                #pragma unroll
                for (int off = 0; off < 25; off++) acc += xp[off] * pwl[co * 25 + off];
                g_feat[(size_t)n * FD + DD + co * 200 + t] = fmaxf(acc, 0.0f);
            }
        }
    }
    if (leaf) {
        for (int j = threadIdx.x; j < DD; j += blockDim.x)
            g_c[(size_t)n * DD + j] = 0.0f;
    }
}

// ---------------- split-K SGEMM: Cz[M,N] = A[M,Kz] @ B[N,Kz]^T --------------
// 128x128x16 tile, 256 threads, 8x8 micro-tile (packed f32x2 FMA).
// gridDim.z = S; slice z writes C + z*strideCz. K % 16 == 0, N % 8 == 0.
__global__ void __launch_bounds__(256, 2)
sgemm128(const float* __restrict__ A, int lda,
         const float* __restrict__ B, int ldb,
         float* __restrict__ C, int ldc, size_t strideCz,
         int M, int N, int K)
{
    __shared__ float As[16][128];
    __shared__ float Bs[16][128];
    const int tid = threadIdx.x;
    const int rowBase = blockIdx.y * 128;
    const int colBase = blockIdx.x * 128;
    const int ldr = tid >> 1;
    const int ldk = (tid & 1) * 8;
    const int w = tid >> 5;
    const int lane = tid & 31;
    const int rm = (w & 3) * 32 + (lane & 3) * 8;
    const int cn = (w >> 2) * 64 + (lane >> 2) * 8;

    const float* Aptr = A + (size_t)(rowBase + ldr) * lda + ldk;
    const float* Bptr = B + (size_t)(colBase + ldr) * ldb + ldk;
    const bool aval = (rowBase + ldr) < M;
    const bool bval = (colBase + ldr) < N;

    // k-slice for this z
    const int ktiles = K >> 4;
    const int S = gridDim.z;
    const int kt0 = (int)(((long long)blockIdx.z * ktiles) / S);
    const int kt1 = (int)(((long long)(blockIdx.z + 1) * ktiles) / S);

    unsigned long long acc2[8][4];
    #pragma unroll
    for (int i = 0; i < 8; i++)
        #pragma unroll
        for (int j = 0; j < 4; j++) acc2[i][j] = 0ull;

    for (int kt = kt0; kt < kt1; kt++) {
        const int k0 = kt << 4;
        float4 a0 = make_float4(0.f,0.f,0.f,0.f), a1 = a0, b0 = a0, b1 = a0;
        if (aval) { a0 = *(const float4*)(Aptr + k0); a1 = *(const float4*)(Aptr + k0 + 4); }
        if (bval) { b0 = *(const float4*)(Bptr + k0); b1 = *(const float4*)(Bptr + k0 + 4); }
        As[ldk+0][ldr]=a0.x; As[ldk+1][ldr]=a0.y; As[ldk+2][ldr]=a0.z; As[ldk+3][ldr]=a0.w;
        As[ldk+4][ldr]=a1.x; As[ldk+5][ldr]=a1.y; As[ldk+6][ldr]=a1.z; As[ldk+7][ldr]=a1.w;
        Bs[ldk+0][ldr]=b0.x; Bs[ldk+1][ldr]=b0.y; Bs[ldk+2][ldr]=b0.z; Bs[ldk+3][ldr]=b0.w;
        Bs[ldk+4][ldr]=b1.x; Bs[ldk+5][ldr]=b1.y; Bs[ldk+6][ldr]=b1.z; Bs[ldk+7][ldr]=b1.w;
        __syncthreads();
        #pragma unroll
        for (int k = 0; k < 16; k++) {
            float4 ra0 = *(const float4*)&As[k][rm];
            float4 ra1 = *(const float4*)&As[k][rm + 4];
            unsigned long long bl0 = *(const unsigned long long*)&Bs[k][cn];
            unsigned long long bl1 = *(const unsigned long long*)&Bs[k][cn + 2];
            unsigned long long bl2 = *(const unsigned long long*)&Bs[k][cn + 4];
            unsigned long long bl3 = *(const unsigned long long*)&Bs[k][cn + 6];
            float av[8] = {ra0.x, ra0.y, ra0.z, ra0.w, ra1.x, ra1.y, ra1.z, ra1.w};
            #pragma unroll
            for (int i = 0; i < 8; i++) {
                unsigned long long a2;
                asm("mov.b64 %0, {%1, %1};" : "=l"(a2) : "f"(av[i]));
                asm("fma.rn.f32x2 %0, %1, %2, %0;" : "+l"(acc2[i][0]) : "l"(a2), "l"(bl0));
                asm("fma.rn.f32x2 %0, %1, %2, %0;" : "+l"(acc2[i][1]) : "l"(a2), "l"(bl1));
                asm("fma.rn.f32x2 %0, %1, %2, %0;" : "+l"(acc2[i][2]) : "l"(a2), "l"(bl2));
                asm("fma.rn.f32x2 %0, %1, %2, %0;" : "+l"(acc2[i][3]) : "l"(a2), "l"(bl3));
            }
        }
        __syncthreads();
    }

    float* Cz = C + (size_t)blockIdx.z * strideCz;
    #pragma unroll
    for (int i = 0; i < 8; i++) {
        int r = rowBase + rm + i;
        if (r < M) {
            float v[8];
            #pragma unroll
            for (int j = 0; j < 4; j++)
                asm("mov.b64 {%0, %1}, %2;" : "=f"(v[2*j]), "=f"(v[2*j+1]) : "l"(acc2[i][j]));
            int c0 = colBase + cn;
            if (c0 < N)
                *(float4*)&Cz[(size_t)r * ldc + c0] = make_float4(v[0], v[1], v[2], v[3]);
            if (c0 + 4 < N)
                *(float4*)&Cz[(size_t)r * ldc + c0 + 4] = make_float4(v[4], v[5], v[6], v[7]);
        }
    }
}

// ---------------- per-level LSTM input build -------------------------------
__global__ void build_xin(int start, const float* __restrict__ idd)
{
    const int t = blockIdx.x;
    const int p = start + t;
    const int l = 2 * p + 1, r = 2 * p + 2;
    const float* hl = &g_feat[(size_t)l * FD + DD];
    const float* hr = &g_feat[(size_t)r * FD + DD];
    float* xiou = &g_xin_iou[(size_t)t * KIN];
    float* xfl  = &g_xin_f[(size_t)(2 * t) * KIN];
    float* xfr  = &g_xin_f[(size_t)(2 * t + 1) * KIN];
    for (int j = threadIdx.x; j < IDDIM; j += blockDim.x) {
        float v = idd[(size_t)p * IDDIM + j];
        xiou[j] = v; xfl[j] = v; xfr[j] = v;
    }
    for (int j = threadIdx.x; j < DD; j += blockDim.x) {
        float a = hl[j], b = hr[j];
        xiou[IDDIM + j] = a + b;
        xfl[IDDIM + j] = a;
        xfr[IDDIM + j] = b;
    }
}

// ---------------- per-level LSTM combine (sums split-K partials) -----------
__global__ void lstm_combine(int start, int m, int S,
                             const float* __restrict__ bi, const float* __restrict__ bf,
                             const float* __restrict__ bu, const float* __restrict__ bo)
{
    const int t = blockIdx.x;
    const int p = start + t;
    const int l = 2 * p + 1, r = 2 * p + 2;
    for (int j = threadIdx.x; j < DD; j += blockDim.x) {
        float si = 0.f, so = 0.f, su = 0.f, sfl = 0.f, sfr = 0.f;
        for (int z = 0; z < S; z++) {
            const float* piou = &g_pre_iou[((size_t)z * m + t) * NIOU];
            si += piou[j];
            so += piou[DD + j];
            su += piou[2 * DD + j];
            const float* pf = &g_pre_f[(size_t)z * 2 * m * DD];
            sfl += pf[(size_t)(2 * t) * DD + j];
            sfr += pf[(size_t)(2 * t + 1) * DD + j];
        }
        float vi = sigmoidf(si + bi[j]);
        float vo = sigmoidf(so + bo[j]);
        float vu = tanhf  (su + bu[j]);
        float fl = sigmoidf(sfl + bf[j]);
        float fr = sigmoidf(sfr + bf[j]);
        float cn = vi * vu + fl * g_c[(size_t)l * DD + j] + fr * g_c[(size_t)r * DD + j];
        g_c[(size_t)p * DD + j] = cn;
        g_feat[(size_t)p * FD + DD + j] = vo * tanhf(cn);
    }
}

// ---------------- pack fc0 weight [192,3232] -------------------------------
__global__ void pack_w012(const float* __restrict__ fc0_w)
{
    int idx = blockIdx.x * blockDim.x + threadIdx.x;
    if (idx >= YW * FD) return;
    int r = idx / FD, k = idx % FD;
    g_w012[idx] = fc0_w[(size_t)(r & 63) * (3 * FD) + (size_t)(r >> 6) * FD + k];
}

// ---------------- head: fusion combine + fc1 + fc2 (sums fc0 partials) -----
__device__ __forceinline__ float ysum(int node, int col)
{
    float s = 0.f;
    #pragma unroll
    for (int z = 0; z < SFC0; z++)
        s += g_y[((size_t)z * NN + node) * YW + col];
    return s;
}

__global__ void head_kernel(const float* __restrict__ fc0_b,
                            const float* __restrict__ fc1_w, const float* __restrict__ fc1_b,
                            const float* __restrict__ fc2_w, const float* __restrict__ fc2_b,
                            float* __restrict__ out)
{
    __shared__ float z[64];
    __shared__ float z1[64];
    __shared__ float partial[2];
    const int n = blockIdx.x;
    const int j = threadIdx.x;

    float acc = fc0_b[j] + ysum(n, j);
    if (n > 0) acc += ysum((n - 1) >> 1, 64 + j);
    if (n < NINT)
        acc += 0.5f * (ysum(2 * n + 1, 128 + j) + ysum(2 * n + 2, 128 + j));
    z[j] = fmaxf(acc, 0.0f);
    __syncthreads();

    float a1 = fc1_b[j];
    #pragma unroll 8
    for (int k = 0; k < 64; k++) a1 += fc1_w[j * 64 + k] * z[k];
    z1[j] = fmaxf(a1, 0.0f);
    __syncthreads();

    float v = fc2_w[j] * z1[j];
    #pragma unroll
    for (int off = 16; off > 0; off >>= 1) v += __shfl_down_sync(0xffffffffu, v, off);
    if ((j & 31) == 0) partial[j >> 5] = v;
    __syncthreads();
    if (j == 0) out[n] = partial[0] + partial[1] + fc2_b[0];
}

// ---------------- launch ----------------------------------------------------
extern "C" void kernel_launch(void* const* d_in, const int* in_sizes, int n_in,
                              void* d_out, int out_size)
{
    const float* x      = (const float*)d_in[0];
    const float* idd    = (const float*)d_in[1];
    const float* conv_w  = (const float*)d_in[4];
    const float* conv_b  = (const float*)d_in[5];
    const float* convl_w = (const float*)d_in[6];
    const float* convl_b = (const float*)d_in[7];
    const float* Wi = (const float*)d_in[8];   const float* bi = (const float*)d_in[9];
    const float* Wf = (const float*)d_in[10];  const float* bf = (const float*)d_in[11];
    const float* Wu = (const float*)d_in[12];  const float* bu = (const float*)d_in[13];
    const float* Wo = (const float*)d_in[14];  const float* bo = (const float*)d_in[15];
    const float* fc0_w = (const float*)d_in[16]; const float* fc0_b = (const float*)d_in[17];
    const float* fc1_w = (const float*)d_in[18]; const float* fc1_b = (const float*)d_in[19];
    const float* fc2_w = (const float*)d_in[20]; const float* fc2_b = (const float*)d_in[21];
    float* out = (float*)d_out;

    float *p_xin_iou, *p_xin_f, *p_pre_iou, *p_pre_f, *p_feat, *p_y, *p_w012, *p_wiou;
    cudaGetSymbolAddress((void**)&p_xin_iou, g_xin_iou);
    cudaGetSymbolAddress((void**)&p_xin_f,   g_xin_f);
    cudaGetSymbolAddress((void**)&p_pre_iou, g_pre_iou);
    cudaGetSymbolAddress((void**)&p_pre_f,   g_pre_f);
    cudaGetSymbolAddress((void**)&p_feat,    g_feat);
    cudaGetSymbolAddress((void**)&p_y,       g_y);
    cudaGetSymbolAddress((void**)&p_w012,    g_w012);
    cudaGetSymbolAddress((void**)&p_wiou,    g_wiou);

    const size_t wbytes = (size_t)DD * KIN * sizeof(float);

    // 0) pack WIOU = [Wi; Wo; Wu]
    cudaMemcpyAsync(p_wiou,                        Wi, wbytes, cudaMemcpyDeviceToDevice, 0);
    cudaMemcpyAsync(p_wiou + (size_t)DD * KIN,     Wo, wbytes, cudaMemcpyDeviceToDevice, 0);
    cudaMemcpyAsync(p_wiou + (size_t)2 * DD * KIN, Wu, wbytes, cudaMemcpyDeviceToDevice, 0);

    // 1) conv front-end
    conv_kernel<<<NN, 256>>>(x, idd, conv_w, conv_b, convl_w, convl_b);

    // 2) pack fc0 weight blocks
    pack_w012<<<(YW * FD + 255) / 256, 256>>>(fc0_w);

    // 3) bottom-up tree LSTM with per-level split-K
    for (int depth = 11; depth >= 0; depth--) {
        int m = 1 << depth;
        int start = m - 1;
        int S = (m >= 2048) ? 1 : (m == 1024) ? 2 : (m == 512) ? 4 : (m == 256) ? 8 : 16;
        build_xin<<<m, 256>>>(start, idd);
        dim3 g1((NIOU + 127) / 128, (m + 127) / 128, S);
        sgemm128<<<g1, 256>>>(p_xin_iou, KIN, p_wiou, KIN,
                              p_pre_iou, NIOU, (size_t)m * NIOU, m, NIOU, KIN);
        dim3 g2((DD + 127) / 128, (2 * m + 127) / 128, S);
        sgemm128<<<g2, 256>>>(p_xin_f, KIN, Wf, KIN,
                              p_pre_f, DD, (size_t)2 * m * DD, 2 * m, DD, KIN);
        lstm_combine<<<m, 256>>>(start, m, S, bi, bf, bu, bo);
    }

    // 4) fused fc0 with split-K=4: Y[z][N,192] = feat @ [W0a;W0b;W0c]^T
    dim3 g3((YW + 127) / 128, (NN + 127) / 128, SFC0);
    sgemm128<<<g3, 256>>>(p_feat, FD, p_w012, FD,
                          p_y, YW, (size_t)NN * YW, NN, YW, FD);

    // 5) fusion combine + fc1 + fc2
    head_kernel<<<NN, 64>>>(fc0_b, fc1_w, fc1_b, fc2_w, fc2_b, out);
}

// round 4
// speedup vs baseline: 3.0605x; 1.6138x over previous
#include <cuda_runtime.h>
#include <cuda_bf16.h>
#include <math.h>
#include <stdint.h>

// ---------------- problem constants ----------------
#define NN     8191
#define NINT   4095
#define SNPX   5000
#define DD     1600
#define IDDIM  32
#define KIN    1632        // DD + IDDIM
#define FD     3232        // 2*DD + IDDIM
#define YW     192         // 3 * 64 fc0 pieces
#define NIOU   4800        // 3 * DD
#define SFC0   4
#define LDS    40          // smem row stride (bf16 elems), 32 data + 8 pad

// ---------------- scratch ----------------
__device__ float g_h[(size_t)NN * DD];
__device__ float g_c[(size_t)NN * DD];
__device__ float g_pre_iou[(size_t)2048 * NIOU];
__device__ float g_pre_f[(size_t)4096 * DD];
__device__ float g_y[(size_t)SFC0 * NN * YW];

__device__ __nv_bfloat16 g_fb_h[(size_t)NN * FD];   // feat hi plane
__device__ __nv_bfloat16 g_fb_l[(size_t)NN * FD];   // feat lo plane
__device__ __nv_bfloat16 g_xiou_h[(size_t)2048 * KIN];
__device__ __nv_bfloat16 g_xiou_l[(size_t)2048 * KIN];
__device__ __nv_bfloat16 g_xf_h[(size_t)4096 * KIN];
__device__ __nv_bfloat16 g_xf_l[(size_t)4096 * KIN];
__device__ __nv_bfloat16 g_wiou_h[(size_t)NIOU * KIN];
__device__ __nv_bfloat16 g_wiou_l[(size_t)NIOU * KIN];
__device__ __nv_bfloat16 g_wf_h[(size_t)DD * KIN];
__device__ __nv_bfloat16 g_wf_l[(size_t)DD * KIN];
__device__ __nv_bfloat16 g_w012h[(size_t)YW * FD];
__device__ __nv_bfloat16 g_w012l[(size_t)YW * FD];

__device__ __forceinline__ float sigmoidf(float x) { return 1.0f / (1.0f + expf(-x)); }

__device__ __forceinline__ void split2(float v, __nv_bfloat16* hi, __nv_bfloat16* lo)
{
    __nv_bfloat16 h = __float2bfloat16(v);
    *hi = h;
    *lo = __float2bfloat16(v - __bfloat162float(h));
}

__device__ __forceinline__ uint32_t smem_u32(const void* p)
{
    uint32_t a;
    asm("{ .reg .u64 t; cvta.to.shared.u64 t, %1; cvt.u32.u64 %0, t; }"
        : "=r"(a) : "l"(p));
    return a;
}

__device__ __forceinline__ void ldm_x4(uint32_t& r0, uint32_t& r1, uint32_t& r2, uint32_t& r3,
                                       const __nv_bfloat16* p)
{
    uint32_t a = smem_u32(p);
    asm volatile("ldmatrix.sync.aligned.m8n8.x4.shared.b16 {%0,%1,%2,%3}, [%4];"
                 : "=r"(r0), "=r"(r1), "=r"(r2), "=r"(r3) : "r"(a));
}

__device__ __forceinline__ void mma_bf16(float* c, const uint32_t* a, const uint32_t* b)
{
    asm volatile("mma.sync.aligned.m16n8k16.row.col.f32.bf16.bf16.f32 "
                 "{%0,%1,%2,%3}, {%4,%5,%6,%7}, {%8,%9}, {%0,%1,%2,%3};"
                 : "+f"(c[0]), "+f"(c[1]), "+f"(c[2]), "+f"(c[3])
                 : "r"(a[0]), "r"(a[1]), "r"(a[2]), "r"(a[3]), "r"(b[0]), "r"(b[1]));
}

// ---------------- conv front-end -------------------------------------------
__global__ void conv_kernel(const float* __restrict__ x,
                            const float* __restrict__ idd,
                            const float* __restrict__ cw, const float* __restrict__ cb,
                            const float* __restrict__ lw, const float* __restrict__ lb)
{
    __shared__ float xs[SNPX];
    __shared__ float pwi[200];
    __shared__ float pwl[200];
    const int n = blockIdx.x;
    const float* xr = x + (size_t)n * SNPX;
    for (int i = threadIdx.x; i < SNPX / 4; i += blockDim.x)
        ((float4*)xs)[i] = ((const float4*)xr)[i];
    if (threadIdx.x < 200) {
        int co = threadIdx.x / 25, off = threadIdx.x % 25;
        int widx = co * 25 + (off % 5) * 5 + (off / 5);
        pwi[threadIdx.x] = cw[widx];
        pwl[threadIdx.x] = lw[widx];
    }
    if (threadIdx.x >= 224) {
        int j = threadIdx.x - 224;
        split2(idd[(size_t)n * IDDIM + j],
               &g_fb_h[(size_t)n * FD + 3200 + j], &g_fb_l[(size_t)n * FD + 3200 + j]);
    }
    __syncthreads();

    const bool leaf = (n >= NINT);
    const int t = threadIdx.x;
    if (t < 200) {
        const float* xp = &xs[25 * t];
        #pragma unroll
        for (int co = 0; co < 8; co++) {
            float acc = cb[co];
            #pragma unroll
            for (int off = 0; off < 25; off++) acc += xp[off] * pwi[co * 25 + off];
            acc = fmaxf(acc, 0.0f);
            size_t o = (size_t)n * FD + co * 200 + t;
            split2(acc, &g_fb_h[o], &g_fb_l[o]);
        }
        if (leaf) {
            #pragma unroll
            for (int co = 0; co < 8; co++) {
                float acc = lb[co];
                #pragma unroll
                for (int off = 0; off < 25; off++) acc += xp[off] * pwl[co * 25 + off];
                acc = fmaxf(acc, 0.0f);
                g_h[(size_t)n * DD + co * 200 + t] = acc;
                size_t o = (size_t)n * FD + DD + co * 200 + t;
                split2(acc, &g_fb_h[o], &g_fb_l[o]);
            }
        }
    }
    if (leaf) {
        for (int j = threadIdx.x; j < DD; j += blockDim.x)
            g_c[(size_t)n * DD + j] = 0.0f;
    }
}

// ---------------- tensor-core GEMM: Cz[M,N] = A[M,Kz] @ B[N,Kz]^T ----------
// bf16 3-term split (ah*bh + ah*bl + al*bh), fp32 accumulate.
// 128x128 tile, 256 threads (2x4 warps, 64x32 warp tile), BK=32.
// K % 32 == 0; M,N guarded. gridDim.z = split-K slices.
__global__ void __launch_bounds__(256)
bmma(const __nv_bfloat16* __restrict__ Ahi, const __nv_bfloat16* __restrict__ Alo, int lda,
     const __nv_bfloat16* __restrict__ Bhi, const __nv_bfloat16* __restrict__ Blo, int ldb,
     float* __restrict__ C, int ldc, size_t strideCz, int M, int N, int K)
{
    __shared__ __align__(16) __nv_bfloat16 As[2][128][LDS];
    __shared__ __align__(16) __nv_bfloat16 Bs[2][128][LDS];
    const int tid = threadIdx.x;
    const int rowBase = blockIdx.y * 128;
    const int colBase = blockIdx.x * 128;
    const int warp = tid >> 5, lane = tid & 31;
    const int wm = (warp & 1) * 64;
    const int wn = (warp >> 1) * 32;

    const int lrow = tid >> 1;
    const int lk = (tid & 1) * 16;
    const bool avalid = (rowBase + lrow) < M;
    const bool bvalid = (colBase + lrow) < N;
    const __nv_bfloat16* Ah = Ahi + (size_t)(rowBase + lrow) * lda + lk;
    const __nv_bfloat16* Al = Alo + (size_t)(rowBase + lrow) * lda + lk;
    const __nv_bfloat16* Bh = Bhi + (size_t)(colBase + lrow) * ldb + lk;
    const __nv_bfloat16* Bl = Blo + (size_t)(colBase + lrow) * ldb + lk;

    const int ktiles = K >> 5;
    const int S = gridDim.z;
    const int kt0 = (int)(((long long)blockIdx.z * ktiles) / S);
    const int kt1 = (int)(((long long)(blockIdx.z + 1) * ktiles) / S);

    float acc[4][4][4];
    #pragma unroll
    for (int a = 0; a < 4; a++)
        #pragma unroll
        for (int b = 0; b < 4; b++)
            #pragma unroll
            for (int d = 0; d < 4; d++) acc[a][b][d] = 0.0f;

    for (int kt = kt0; kt < kt1; kt++) {
        const int k0 = kt << 5;
        uint4 z4 = make_uint4(0u, 0u, 0u, 0u);
        uint4 va0 = z4, va1 = z4, vl0 = z4, vl1 = z4;
        uint4 vb0 = z4, vb1 = z4, wb0 = z4, wb1 = z4;
        if (avalid) {
            va0 = *(const uint4*)(Ah + k0); va1 = *(const uint4*)(Ah + k0 + 8);
            vl0 = *(const uint4*)(Al + k0); vl1 = *(const uint4*)(Al + k0 + 8);
        }
        if (bvalid) {
            vb0 = *(const uint4*)(Bh + k0); vb1 = *(const uint4*)(Bh + k0 + 8);
            wb0 = *(const uint4*)(Bl + k0); wb1 = *(const uint4*)(Bl + k0 + 8);
        }
        __syncthreads();
        *(uint4*)&As[0][lrow][lk]     = va0; *(uint4*)&As[0][lrow][lk + 8] = va1;
        *(uint4*)&As[1][lrow][lk]     = vl0; *(uint4*)&As[1][lrow][lk + 8] = vl1;
        *(uint4*)&Bs[0][lrow][lk]     = vb0; *(uint4*)&Bs[0][lrow][lk + 8] = vb1;
        *(uint4*)&Bs[1][lrow][lk]     = wb0; *(uint4*)&Bs[1][lrow][lk + 8] = wb1;
        __syncthreads();

        #pragma unroll
        for (int ks = 0; ks < 2; ks++) {
            uint32_t afh[4][4], afl[4][4];
            #pragma unroll
            for (int mt = 0; mt < 4; mt++) {
                const int r = wm + mt * 16 + (lane & 15);
                const int c = ks * 16 + (lane >> 4) * 8;
                ldm_x4(afh[mt][0], afh[mt][1], afh[mt][2], afh[mt][3], &As[0][r][c]);
                ldm_x4(afl[mt][0], afl[mt][1], afl[mt][2], afl[mt][3], &As[1][r][c]);
            }
            uint32_t bfh[4][2], bfl[4][2];
            #pragma unroll
            for (int nt = 0; nt < 4; nt++) {
                const int nr = wn + nt * 8 + (lane >> 2);
                const int kk = ks * 16 + (lane & 3) * 2;
                bfh[nt][0] = *(const uint32_t*)&Bs[0][nr][kk];
                bfh[nt][1] = *(const uint32_t*)&Bs[0][nr][kk + 8];
                bfl[nt][0] = *(const uint32_t*)&Bs[1][nr][kk];
                bfl[nt][1] = *(const uint32_t*)&Bs[1][nr][kk + 8];
            }
            #pragma unroll
            for (int mt = 0; mt < 4; mt++)
                #pragma unroll
                for (int nt = 0; nt < 4; nt++) {
                    mma_bf16(acc[mt][nt], afh[mt], bfh[nt]);
                    mma_bf16(acc[mt][nt], afh[mt], bfl[nt]);
                    mma_bf16(acc[mt][nt], afl[mt], bfh[nt]);
                }
        }
    }

    float* Cz = C + (size_t)blockIdx.z * strideCz;
    #pragma unroll
    for (int mt = 0; mt < 4; mt++) {
        int r0 = rowBase + wm + mt * 16 + (lane >> 2);
        #pragma unroll
        for (int nt = 0; nt < 4; nt++) {
            int c = colBase + wn + nt * 8 + (lane & 3) * 2;
            if (c < N) {
                if (r0 < M) {
                    Cz[(size_t)r0 * ldc + c]     = acc[mt][nt][0];
                    Cz[(size_t)r0 * ldc + c + 1] = acc[mt][nt][1];
                }
                if (r0 + 8 < M) {
                    Cz[(size_t)(r0 + 8) * ldc + c]     = acc[mt][nt][2];
                    Cz[(size_t)(r0 + 8) * ldc + c + 1] = acc[mt][nt][3];
                }
            }
        }
    }
}

// ---------------- weight split --------------------------------------------
__global__ void split_arr(const float* __restrict__ s, __nv_bfloat16* __restrict__ hi,
                          __nv_bfloat16* __restrict__ lo, int n)
{
    int i = blockIdx.x * blockDim.x + threadIdx.x;
    if (i < n) split2(s[i], &hi[i], &lo[i]);
}

// ---------------- pack + split fc0 weight [192,3232] -----------------------
__global__ void pack_w012(const float* __restrict__ fc0_w)
{
    int idx = blockIdx.x * blockDim.x + threadIdx.x;
    if (idx >= YW * FD) return;
    int r = idx / FD, k = idx % FD;
    float v = fc0_w[(size_t)(r & 63) * (3 * FD) + (size_t)(r >> 6) * FD + k];
    split2(v, &g_w012h[idx], &g_w012l[idx]);
}

// ---------------- per-level LSTM input build -------------------------------
__global__ void build_xin(int start, const float* __restrict__ idd)
{
    const int t = blockIdx.x;
    const int p = start + t;
    const int l = 2 * p + 1, r = 2 * p + 2;
    const float* hl = &g_h[(size_t)l * DD];
    const float* hr = &g_h[(size_t)r * DD];
    const size_t oiou = (size_t)t * KIN;
    const size_t ofl  = (size_t)(2 * t) * KIN;
    const size_t ofr  = (size_t)(2 * t + 1) * KIN;
    for (int j = threadIdx.x; j < IDDIM; j += blockDim.x) {
        float v = idd[(size_t)p * IDDIM + j];
        __nv_bfloat16 h, lo2;
        split2(v, &h, &lo2);
        g_xiou_h[oiou + j] = h; g_xiou_l[oiou + j] = lo2;
        g_xf_h[ofl + j] = h;    g_xf_l[ofl + j] = lo2;
        g_xf_h[ofr + j] = h;    g_xf_l[ofr + j] = lo2;
    }
    for (int j = threadIdx.x; j < DD; j += blockDim.x) {
        float a = hl[j], b = hr[j];
        split2(a + b, &g_xiou_h[oiou + IDDIM + j], &g_xiou_l[oiou + IDDIM + j]);
        split2(a, &g_xf_h[ofl + IDDIM + j], &g_xf_l[ofl + IDDIM + j]);
        split2(b, &g_xf_h[ofr + IDDIM + j], &g_xf_l[ofr + IDDIM + j]);
    }
}

// ---------------- per-level LSTM combine (sums split-K partials) -----------
__global__ void lstm_combine(int start, int m, int S,
                             const float* __restrict__ bi, const float* __restrict__ bf,
                             const float* __restrict__ bu, const float* __restrict__ bo)
{
    const int t = blockIdx.x;
    const int p = start + t;
    const int l = 2 * p + 1, r = 2 * p + 2;
    for (int j = threadIdx.x; j < DD; j += blockDim.x) {
        float si = 0.f, so = 0.f, su = 0.f, sfl = 0.f, sfr = 0.f;
        for (int z = 0; z < S; z++) {
            const float* piou = &g_pre_iou[((size_t)z * m + t) * NIOU];
            si += piou[j];
            so += piou[DD + j];
            su += piou[2 * DD + j];
            const float* pf = &g_pre_f[(size_t)z * 2 * m * DD];
            sfl += pf[(size_t)(2 * t) * DD + j];
            sfr += pf[(size_t)(2 * t + 1) * DD + j];
        }
        float vi = sigmoidf(si + bi[j]);
        float vo = sigmoidf(so + bo[j]);
        float vu = tanhf  (su + bu[j]);
        float fl = sigmoidf(sfl + bf[j]);
        float fr = sigmoidf(sfr + bf[j]);
        float cn = vi * vu + fl * g_c[(size_t)l * DD + j] + fr * g_c[(size_t)r * DD + j];
        float hn = vo * tanhf(cn);
        g_c[(size_t)p * DD + j] = cn;
        g_h[(size_t)p * DD + j] = hn;
        size_t o = (size_t)p * FD + DD + j;
        split2(hn, &g_fb_h[o], &g_fb_l[o]);
    }
}

// ---------------- head: fusion combine + fc1 + fc2 -------------------------
__device__ __forceinline__ float ysum(int node, int col)
{
    float s = 0.f;
    #pragma unroll
    for (int z = 0; z < SFC0; z++)
        s += g_y[((size_t)z * NN + node) * YW + col];
    return s;
}

__global__ void head_kernel(const float* __restrict__ fc0_b,
                            const float* __restrict__ fc1_w, const float* __restrict__ fc1_b,
                            const float* __restrict__ fc2_w, const float* __restrict__ fc2_b,
                            float* __restrict__ out)
{
    __shared__ float z[64];
    __shared__ float z1[64];
    __shared__ float partial[2];
    const int n = blockIdx.x;
    const int j = threadIdx.x;

    float acc = fc0_b[j] + ysum(n, j);
    if (n > 0) acc += ysum((n - 1) >> 1, 64 + j);
    if (n < NINT)
        acc += 0.5f * (ysum(2 * n + 1, 128 + j) + ysum(2 * n + 2, 128 + j));
    z[j] = fmaxf(acc, 0.0f);
    __syncthreads();

    float a1 = fc1_b[j];
    #pragma unroll 8
    for (int k = 0; k < 64; k++) a1 += fc1_w[j * 64 + k] * z[k];
    z1[j] = fmaxf(a1, 0.0f);
    __syncthreads();

    float v = fc2_w[j] * z1[j];
    #pragma unroll
    for (int off = 16; off > 0; off >>= 1) v += __shfl_down_sync(0xffffffffu, v, off);
    if ((j & 31) == 0) partial[j >> 5] = v;
    __syncthreads();
    if (j == 0) out[n] = partial[0] + partial[1] + fc2_b[0];
}

// ---------------- launch ----------------------------------------------------
extern "C" void kernel_launch(void* const* d_in, const int* in_sizes, int n_in,
                              void* d_out, int out_size)
{
    const float* x      = (const float*)d_in[0];
    const float* idd    = (const float*)d_in[1];
    const float* conv_w  = (const float*)d_in[4];
    const float* conv_b  = (const float*)d_in[5];
    const float* convl_w = (const float*)d_in[6];
    const float* convl_b = (const float*)d_in[7];
    const float* Wi = (const float*)d_in[8];   const float* bi = (const float*)d_in[9];
    const float* Wf = (const float*)d_in[10];  const float* bf = (const float*)d_in[11];
    const float* Wu = (const float*)d_in[12];  const float* bu = (const float*)d_in[13];
    const float* Wo = (const float*)d_in[14];  const float* bo = (const float*)d_in[15];
    const float* fc0_w = (const float*)d_in[16]; const float* fc0_b = (const float*)d_in[17];
    const float* fc1_w = (const float*)d_in[18]; const float* fc1_b = (const float*)d_in[19];
    const float* fc2_w = (const float*)d_in[20]; const float* fc2_b = (const float*)d_in[21];
    float* out = (float*)d_out;

    float *p_pre_iou, *p_pre_f, *p_y;
    __nv_bfloat16 *p_xiou_h, *p_xiou_l, *p_xf_h, *p_xf_l;
    __nv_bfloat16 *p_wiou_h, *p_wiou_l, *p_wf_h, *p_wf_l;
    __nv_bfloat16 *p_fb_h, *p_fb_l, *p_w012h, *p_w012l;
    cudaGetSymbolAddress((void**)&p_pre_iou, g_pre_iou);
    cudaGetSymbolAddress((void**)&p_pre_f,   g_pre_f);
    cudaGetSymbolAddress((void**)&p_y,       g_y);
    cudaGetSymbolAddress((void**)&p_xiou_h,  g_xiou_h);
    cudaGetSymbolAddress((void**)&p_xiou_l,  g_xiou_l);
    cudaGetSymbolAddress((void**)&p_xf_h,    g_xf_h);
    cudaGetSymbolAddress((void**)&p_xf_l,    g_xf_l);
    cudaGetSymbolAddress((void**)&p_wiou_h,  g_wiou_h);
    cudaGetSymbolAddress((void**)&p_wiou_l,  g_wiou_l);
    cudaGetSymbolAddress((void**)&p_wf_h,    g_wf_h);
    cudaGetSymbolAddress((void**)&p_wf_l,    g_wf_l);
    cudaGetSymbolAddress((void**)&p_fb_h,    g_fb_h);
    cudaGetSymbolAddress((void**)&p_fb_l,    g_fb_l);
    cudaGetSymbolAddress((void**)&p_w012h,   g_w012h);
    cudaGetSymbolAddress((void**)&p_w012l,   g_w012l);

    const int WN = DD * KIN;  // one gate weight elem count

    // 0) split weights into bf16 hi/lo planes
    split_arr<<<(WN + 255) / 256, 256>>>(Wi, p_wiou_h,          p_wiou_l,          WN);
    split_arr<<<(WN + 255) / 256, 256>>>(Wo, p_wiou_h + WN,     p_wiou_l + WN,     WN);
    split_arr<<<(WN + 255) / 256, 256>>>(Wu, p_wiou_h + 2 * WN, p_wiou_l + 2 * WN, WN);
    split_arr<<<(WN + 255) / 256, 256>>>(Wf, p_wf_h, p_wf_l, WN);
    pack_w012<<<(YW * FD + 255) / 256, 256>>>(fc0_w);

    // 1) conv front-end
    conv_kernel<<<NN, 256>>>(x, idd, conv_w, conv_b, convl_w, convl_b);

    // 2) bottom-up tree LSTM with per-level split-K
    for (int depth = 11; depth >= 0; depth--) {
        int m = 1 << depth;
        int start = m - 1;
        int S = (m >= 2048) ? 1 : (m == 1024) ? 2 : (m == 512) ? 4 : (m == 256) ? 8 : 16;
        build_xin<<<m, 256>>>(start, idd);
        dim3 g1((NIOU + 127) / 128, (m + 127) / 128, S);
        bmma<<<g1, 256>>>(p_xiou_h, p_xiou_l, KIN, p_wiou_h, p_wiou_l, KIN,
                          p_pre_iou, NIOU, (size_t)m * NIOU, m, NIOU, KIN);
        dim3 g2((DD + 127) / 128, (2 * m + 127) / 128, S);
        bmma<<<g2, 256>>>(p_xf_h, p_xf_l, KIN, p_wf_h, p_wf_l, KIN,
                          p_pre_f, DD, (size_t)2 * m * DD, 2 * m, DD, KIN);
        lstm_combine<<<m, 256>>>(start, m, S, bi, bf, bu, bo);
    }

    // 3) fused fc0 with split-K=4: Y = feat @ [W0a;W0b;W0c]^T
    dim3 g3((YW + 127) / 128, (NN + 127) / 128, SFC0);
    bmma<<<g3, 256>>>(p_fb_h, p_fb_l, FD, p_w012h, p_w012l, FD,
                      p_y, YW, (size_t)NN * YW, NN, YW, FD);

    // 4) fusion combine + fc1 + fc2
    head_kernel<<<NN, 64>>>(fc0_b, fc1_w, fc1_b, fc2_w, fc2_b, out);
}